// round 17
// baseline (speedup 1.0000x reference)
#include <cuda_runtime.h>
#include <cuda_fp16.h>
#include <cstdint>

#define CIN    128
#define OUTC   128
#define T_IN   32768
#define P_OUT  32769
#define PTILE  256
#define NTILES3 1032         // 129 p-tiles(256 pos) * 8 batches
#define GRID   148           // persistent, 1 CTA/SM
#define THREADS 512

#define WP 132               // u64 pitch, W pair rows (conflict-free LDS.64)
#define XPF 264              // f32 pitch of x rows (1056B; bank = 8t+g, conflict-free)
#define ROW_B 1056
#define NSTAGE 4
#define LOOKAHEAD 3
#define CHUNK_B (8 * ROW_B)  // 8448 B (8 channels x 264 f32)

// smem byte offsets (102016 B -> 1 CTA/SM)
#define SM_W    0                      // u64 [64][WP] = 67584
#define SM_X    67584                  // 4 stages x 8448 = 33792
#define SM_BIAS 101376                 // 512
#define SM_MBAR 101888                 // 4 full + 4 empty = 64
#define SM_TOT  102016

typedef unsigned long long u64;

__device__ __align__(16) u64 g_W64[64 * WP];

__device__ __forceinline__ uint32_t smem_u32(const void* p) {
    uint32_t a;
    asm("{ .reg .u64 t; cvta.to.shared.u64 t, %1; cvt.u32.u64 %0, t; }" : "=r"(a) : "l"(p));
    return a;
}
__device__ __forceinline__ uint32_t cvt2h(float hi, float lo) {
    uint32_t r;
    asm("cvt.rn.f16x2.f32 %0, %1, %2;" : "=r"(r) : "f"(hi), "f"(lo));
    return r;
}
__device__ __forceinline__ void mma16816h(float* d, const uint32_t* a, uint32_t b0, uint32_t b1) {
    asm volatile(
        "mma.sync.aligned.m16n8k16.row.col.f32.f16.f16.f32 "
        "{%0,%1,%2,%3}, {%4,%5,%6,%7}, {%8,%9}, {%0,%1,%2,%3};"
        : "+f"(d[0]), "+f"(d[1]), "+f"(d[2]), "+f"(d[3])
        : "r"(a[0]), "r"(a[1]), "r"(a[2]), "r"(a[3]), "r"(b0), "r"(b1));
}
__device__ __forceinline__ void mbar_init(uint32_t m, uint32_t cnt) {
    asm volatile("mbarrier.init.shared.b64 [%0], %1;" :: "r"(m), "r"(cnt) : "memory");
}
__device__ __forceinline__ void mbar_expect_tx(uint32_t m, uint32_t bytes) {
    asm volatile("mbarrier.arrive.expect_tx.shared.b64 _, [%0], %1;" :: "r"(m), "r"(bytes) : "memory");
}
__device__ __forceinline__ void mbar_arrive(uint32_t m) {
    asm volatile("mbarrier.arrive.shared.b64 _, [%0];" :: "r"(m) : "memory");
}
__device__ __forceinline__ void mbar_wait(uint32_t m, uint32_t parity) {
    asm volatile(
        "{\n\t.reg .pred P1;\n\t"
        "WAIT_%=:\n\t"
        "mbarrier.try_wait.parity.acquire.cta.shared::cta.b64 P1, [%0], %1, 0x989680;\n\t"
        "@P1 bra.uni DONE_%=;\n\t"
        "bra.uni WAIT_%=;\n\t"
        "DONE_%=:\n\t}" :: "r"(m), "r"(parity) : "memory");
}
__device__ __forceinline__ void bulk_g2s(uint32_t dst, const void* src, uint32_t bytes, uint32_t mbar) {
    asm volatile(
        "cp.async.bulk.shared::cta.global.mbarrier::complete_tx::bytes [%0], [%1], %2, [%3];"
        :: "r"(dst), "l"(src), "r"(bytes), "r"(mbar) : "memory");
}

__global__ void prep_W(const float* __restrict__ W) {
    int idx = blockIdx.x * blockDim.x + threadIdx.x;   // 8192
    int pr = idx >> 7, o = idx & 127;
    int r = ((pr >> 2) << 3) | (pr & 3);
    uint32_t pa = cvt2h(W[o * 256 + 2 * r + 1],       W[o * 256 + 2 * r]);
    uint32_t pb = cvt2h(W[o * 256 + 2 * (r + 4) + 1], W[o * 256 + 2 * (r + 4)]);
    g_W64[pr * WP + o] = ((u64)pb << 32) | pa;
}

// Producer (warp 0): stage chunk jj (one k-step: 8 channels x 260 valid f32).
__device__ __forceinline__ void produce(const float* __restrict__ x, char* smem,
                                        int jj, int sid, int lane,
                                        uint32_t xb, uint32_t mb) {
    const int s = jj & (NSTAGE - 1);
    const uint32_t full  = mb + (uint32_t)s * 8;
    const uint32_t empty = mb + 32 + (uint32_t)s * 8;
    if (jj >= NSTAGE) mbar_wait(empty, (uint32_t)(((jj - NSTAGE) >> 2) & 1));

    const int tile = sid + (jj >> 4) * GRID;
    const int b = tile & 7;
    const long p0 = (long)(tile >> 3) * PTILE;
    const int cb = (jj & 15) * 8;               // channel base of this k-step
    const uint32_t slot = xb + (uint32_t)s * CHUNK_B;

    long vf = (long)T_IN - p0;                  // valid f32 from p0 (multiple of 256, or <=0)
    int vbytes = (vf >= 260) ? 1040 : (vf > 0 ? (int)vf * 4 : 0);   // 1040 / 1024 / 0

    if (vbytes < 1040) {
        char* slotp = smem + SM_X + (size_t)s * CHUNK_B;
        if (vbytes == 0) {
            for (int i = lane; i < CHUNK_B / 16; i += 32)
                *reinterpret_cast<uint4*>(slotp + i * 16) = make_uint4(0, 0, 0, 0);
        } else if (lane < 8) {
            // zero floats [256,260) of each row (read range ends at 257)
            *reinterpret_cast<uint4*>(slotp + lane * ROW_B + 1024) = make_uint4(0, 0, 0, 0);
        }
        __syncwarp();
    }
    if (lane == 0) {
        if (vbytes > 0) mbar_expect_tx(full, (uint32_t)(8 * vbytes));
        else            mbar_arrive(full);
    }
    __syncwarp();
    if (lane < 8 && vbytes > 0) {
        const float* src = x + ((size_t)b * CIN + (size_t)(cb + lane)) * T_IN + p0;
        bulk_g2s(slot + (uint32_t)lane * ROW_B, src, (uint32_t)vbytes, full);
    }
}

__global__ __launch_bounds__(THREADS, 1)
void dconv17(const float* __restrict__ x,
             const float* __restrict__ bias,
             float* __restrict__ out)
{
    extern __shared__ char smem[];
    u64*   sW    = reinterpret_cast<u64*>(smem + SM_W);
    float* sBias = reinterpret_cast<float*>(smem + SM_BIAS);

    const int tid = threadIdx.x;
    const int lane = tid & 31;
    const int t = lane & 3;
    const int g = lane >> 2;
    const int wid = tid >> 5;
    const int ob   = (wid >> 3) * 64;   // M: output base (2 groups of 64)
    const int pgrp = wid & 7;           // N: 32-position group (8 groups = 256 pos)

    const uint32_t sb = smem_u32(smem);
    const uint32_t xb = sb + SM_X;
    const uint32_t mb = sb + SM_MBAR;
    const float* sX = reinterpret_cast<const float*>(smem + SM_X);

    const int sid = blockIdx.x;
    const int nt  = (NTILES3 - 1 - sid) / GRID + 1;   // 6 or 7 tiles
    const int nc  = nt * 16;

    // one-time: W image + bias + mbarrier init
    {
        const uint4* src = reinterpret_cast<const uint4*>(g_W64);
        uint4* dst = reinterpret_cast<uint4*>(sW);
        #pragma unroll 4
        for (int i = tid; i < 4224; i += THREADS) dst[i] = src[i];
    }
    if (tid < 128) sBias[tid] = bias[tid];
    if (tid == 0) {
        #pragma unroll
        for (int s = 0; s < NSTAGE; ++s) {
            mbar_init(mb + s * 8, 1);         // full: tx-based
            mbar_init(mb + 32 + s * 8, 16);   // empty: 16 warps
        }
    }
    __syncthreads();

    float acc[4][4][4];
    #pragma unroll
    for (int mf = 0; mf < 4; ++mf)
        #pragma unroll
        for (int nf = 0; nf < 4; ++nf)
            #pragma unroll
            for (int i = 0; i < 4; ++i) acc[mf][nf][i] = 0.0f;

    if (wid == 0) {
        #pragma unroll
        for (int j0 = 0; j0 < LOOKAHEAD; ++j0)
            if (j0 < nc) produce(x, smem, j0, sid, lane, xb, mb);
    }

    int j = 0;
    for (int tt = 0; tt < nt; ++tt) {
        #pragma unroll 1
        for (int cc = 0; cc < 16; ++cc, ++j) {
            if (wid == 0 && j + LOOKAHEAD < nc)
                produce(x, smem, j + LOOKAHEAD, sid, lane, xb, mb);

            const int s = j & (NSTAGE - 1);
            mbar_wait(mb + (uint32_t)s * 8, (uint32_t)((j >> 2) & 1));

            // ---- consume chunk: one k-step over 256 positions ----
            const float* Xc = sX + (size_t)s * (CHUNK_B / 4);
            const float* xr = Xc + (size_t)t * XPF + pgrp * 32 + g;
            uint32_t bf[8];
            #pragma unroll
            for (int nf = 0; nf < 4; ++nf) {
                float v0 = xr[8 * nf],          v2 = xr[8 * nf + 2];
                float w0 = xr[4 * XPF + 8 * nf], w2 = xr[4 * XPF + 8 * nf + 2];
                bf[2 * nf]     = cvt2h(v2, v0);
                bf[2 * nf + 1] = cvt2h(w2, w0);
            }
            const u64* wr = sW + (size_t)(4 * cc + t) * WP;
            #pragma unroll
            for (int mf = 0; mf < 4; ++mf) {
                const int o = ob + 16 * mf + g;
                u64 wA = wr[o], wB = wr[o + 8];
                uint32_t a[4] = { (uint32_t)wA, (uint32_t)wB,
                                  (uint32_t)(wA >> 32), (uint32_t)(wB >> 32) };
                #pragma unroll
                for (int nf = 0; nf < 4; ++nf)
                    mma16816h(acc[mf][nf], a, bf[2 * nf], bf[2 * nf + 1]);
            }
            if (lane == 0) mbar_arrive(mb + 32 + (uint32_t)s * 8);   // empty (per warp)
        }

        // ---- tile boundary: epilogue ----
        {
            const int tile = sid + tt * GRID;
            const int b = tile & 7;
            const long p0 = (long)(tile >> 3) * PTILE;
            #pragma unroll
            for (int mf = 0; mf < 4; ++mf) {
                const int o = ob + 16 * mf + g;
                const float b0 = sBias[o], b1 = sBias[o + 8];
                #pragma unroll
                for (int nf = 0; nf < 4; ++nf) {
                    long p = p0 + pgrp * 32 + 8 * nf + 2 * t;
                    float* r0 = out + ((size_t)b * OUTC + o) * P_OUT + p;
                    float* r1 = r0 + (size_t)8 * P_OUT;
                    if (p < P_OUT) {
                        r0[0] = acc[mf][nf][0] + b0;
                        r1[0] = acc[mf][nf][2] + b1;
                    }
                    if (p + 1 < P_OUT) {
                        r0[1] = acc[mf][nf][1] + b0;
                        r1[1] = acc[mf][nf][3] + b1;
                    }
                    #pragma unroll
                    for (int k = 0; k < 4; ++k) acc[mf][nf][k] = 0.0f;
                }
            }
        }
    }
}

extern "C" void kernel_launch(void* const* d_in, const int* in_sizes, int n_in,
                              void* d_out, int out_size)
{
    const float* x  = (const float*)d_in[0];   // (8, 128, 32768)
    const float* W  = (const float*)d_in[1];   // (128, 128, 2)
    const float* bs = (const float*)d_in[2];   // (128,)
    float* out = (float*)d_out;                // (8, 128, 32769)

    cudaFuncSetAttribute(dconv17, cudaFuncAttributeMaxDynamicSharedMemorySize, SM_TOT);

    prep_W<<<32, 256>>>(W);
    dconv17<<<GRID, THREADS, SM_TOT>>>(x, bs, out);
}